// round 8
// baseline (speedup 1.0000x reference)
#include <cuda_runtime.h>
#include <cuda_bf16.h>

// One exact wave: 148 SMs x 6 resident blocks (regs=37 -> 6 blocks/SM @ 256 thr)
static constexpr int WAVE_BLOCKS = 148 * 6;   // 888

__device__ double        g_part[WAVE_BLOCKS];
__device__ unsigned int  g_ticket = 0;        // self-resetting, graph-replay safe

__device__ __forceinline__ float row_term(float i0, float i1, float i2,
                                          int t0, int t1, int t2, int cs,
                                          const float* __restrict__ w,
                                          float invB) {
    // sample weight: class {100..700} -> index t2/100 - 1
    float sw = w[t2 / 100 - 1];
    float f0 = (float)t0, f1 = (float)t1, f2 = (float)t2;
    float d0 = i0 - f0, d1 = i1 - f1, d2 = i2 - f2;
    // sensors .mean(axis=1) -> 0.5*(d0^2+d1^2); anomaly -> d2^2; /B folded via invB
    float main_t = sw * (0.5f * (d0 * d0 + d1 * d1) + d2 * d2);

    // R02: lo = 6400 (state 4), 6000 (states 5-8), else 11500 ; hi = 12000
    float r02lo = (cs == 4) ? 6400.0f
                 : ((unsigned)(cs - 5) <= 3u ? 6000.0f : 11500.0f);
    // R03: lo = 2200 ; hi = 13000 (state 8) else 2500
    float r03hi = (cs == 8) ? 13000.0f : 2500.0f;

    float b0 = fminf(f0 - r02lo, 0.0f);
    float a0 = fmaxf(f0 - 12000.0f, 0.0f);
    float b1 = fminf(f1 - 2200.0f, 0.0f);
    float a1 = fmaxf(f1 - r03hi, 0.0f);
    float p = b0 * b0 + a0 * a0 + b1 * b1 + a1 * a1;

    return fmaf(main_t, invB, p);
}

__global__ void __launch_bounds__(256)
fused_loss_kernel(const float* __restrict__ inputs,
                  const int* __restrict__ targets,
                  const int* __restrict__ cycle_states,
                  const float* __restrict__ weights,
                  float* __restrict__ out,
                  int nrows) {
    __shared__ float w[7];
    if (threadIdx.x < 7) w[threadIdx.x] = weights[threadIdx.x];
    __syncthreads();

    const float invB = 1.0f / (float)nrows;
    const float4* __restrict__ in4 = (const float4*)inputs;
    const int4*   __restrict__ tg4 = (const int4*)targets;
    const int4*   __restrict__ cs4 = (const int4*)cycle_states;

    double acc = 0.0;
    int nquad  = nrows >> 2;  // 4 rows per iteration (3 float4 + 3 int4 + 1 int4)
    int stride = gridDim.x * blockDim.x;
    for (int q = blockIdx.x * blockDim.x + threadIdx.x; q < nquad; q += stride) {
        float4 ia = in4[3 * q + 0];
        float4 ib = in4[3 * q + 1];
        float4 ic = in4[3 * q + 2];
        int4   ta = tg4[3 * q + 0];
        int4   tb = tg4[3 * q + 1];
        int4   tc = tg4[3 * q + 2];
        int4   cs = cs4[q];

        // rows: (ia.x,ia.y,ia.z) (ia.w,ib.x,ib.y) (ib.z,ib.w,ic.x) (ic.y,ic.z,ic.w)
        float s = row_term(ia.x, ia.y, ia.z, ta.x, ta.y, ta.z, cs.x, w, invB)
                + row_term(ia.w, ib.x, ib.y, ta.w, tb.x, tb.y, cs.y, w, invB)
                + row_term(ib.z, ib.w, ic.x, tb.z, tb.w, tc.x, cs.z, w, invB)
                + row_term(ic.y, ic.z, ic.w, tc.y, tc.z, tc.w, cs.w, w, invB);
        acc += (double)s;   // one FP64 add per 4 rows
    }

    // intra-block reduce (double)
    #pragma unroll
    for (int o = 16; o; o >>= 1)
        acc += __shfl_down_sync(0xffffffffu, acc, o);

    __shared__ double sm[8];
    if ((threadIdx.x & 31) == 0) sm[threadIdx.x >> 5] = acc;
    __syncthreads();

    __shared__ bool s_last;
    if (threadIdx.x == 0) {
        double v = sm[0];
        #pragma unroll
        for (int i = 1; i < 8; i++) v += sm[i];
        g_part[blockIdx.x] = v;
        __threadfence();
        unsigned int t = atomicAdd(&g_ticket, 1u);
        s_last = (t == gridDim.x - 1);
        if (s_last) g_ticket = 0;   // reset for next graph replay
    }
    __syncthreads();

    // last block reduces all partials and writes the scalar
    if (s_last) {
        __threadfence();
        double v = 0.0;
        for (int i = threadIdx.x; i < (int)gridDim.x; i += 256)
            v += g_part[i];
        #pragma unroll
        for (int o = 16; o; o >>= 1)
            v += __shfl_down_sync(0xffffffffu, v, o);
        if ((threadIdx.x & 31) == 0) sm[threadIdx.x >> 5] = v;
        __syncthreads();
        if (threadIdx.x == 0) {
            double tot = sm[0];
            #pragma unroll
            for (int i = 1; i < 8; i++) tot += sm[i];
            out[0] = (float)tot;
        }
    }
}

extern "C" void kernel_launch(void* const* d_in, const int* in_sizes, int n_in,
                              void* d_out, int out_size) {
    const float* inputs       = (const float*)d_in[0];   // [B,3] f32
    const int*   targets      = (const int*)d_in[1];     // [B,3] i32
    const int*   cycle_states = (const int*)d_in[2];     // [B]   i32
    const float* weights      = (const float*)d_in[3];   // [7]   f32
    float* out = (float*)d_out;

    int nrows = in_sizes[0] / 3;  // 4,194,304

    const int threads = 256;
    int nquad = nrows >> 2;
    int blocks = (nquad + threads - 1) / threads;
    if (blocks > WAVE_BLOCKS) blocks = WAVE_BLOCKS;  // exactly one wave
    fused_loss_kernel<<<blocks, threads>>>(inputs, targets, cycle_states,
                                           weights, out, nrows);
}

// round 9
// speedup vs baseline: 1.3648x; 1.3648x over previous
#include <cuda_runtime.h>
#include <cuda_bf16.h>

// Full-occupancy single wave: 148 SMs x 8 blocks/SM (regs forced <=32)
static constexpr int WAVE_BLOCKS = 148 * 8;   // 1184

__device__ double        g_part[WAVE_BLOCKS];
__device__ unsigned int  g_ticket = 0;        // self-resetting, graph-replay safe

__device__ __forceinline__ float row_term(float i0, float i1, float i2,
                                          int t0, int t1, int t2, int cs,
                                          const float* __restrict__ w,
                                          float invB) {
    // sample weight: class {100..700} -> index t2/100 - 1
    float sw = w[t2 / 100 - 1];
    float f0 = (float)t0, f1 = (float)t1, f2 = (float)t2;
    float d0 = i0 - f0, d1 = i1 - f1, d2 = i2 - f2;
    // sensors .mean(axis=1) -> 0.5*(d0^2+d1^2); anomaly -> d2^2; /B folded via invB
    float main_t = sw * (0.5f * (d0 * d0 + d1 * d1) + d2 * d2);

    // R02: lo = 6400 (state 4), 6000 (states 5-8), else 11500 ; hi = 12000
    float r02lo = (cs == 4) ? 6400.0f
                 : ((unsigned)(cs - 5) <= 3u ? 6000.0f : 11500.0f);
    // R03: lo = 2200 ; hi = 13000 (state 8) else 2500
    float r03hi = (cs == 8) ? 13000.0f : 2500.0f;

    float b0 = fminf(f0 - r02lo, 0.0f);
    float a0 = fmaxf(f0 - 12000.0f, 0.0f);
    float b1 = fminf(f1 - 2200.0f, 0.0f);
    float a1 = fmaxf(f1 - r03hi, 0.0f);
    float p = b0 * b0 + a0 * a0 + b1 * b1 + a1 * a1;

    return fmaf(main_t, invB, p);
}

__global__ void __launch_bounds__(256, 8)
fused_loss_kernel(const float* __restrict__ inputs,
                  const int* __restrict__ targets,
                  const int* __restrict__ cycle_states,
                  const float* __restrict__ weights,
                  float* __restrict__ out,
                  int nrows) {
    __shared__ float w[7];
    if (threadIdx.x < 7) w[threadIdx.x] = weights[threadIdx.x];
    __syncthreads();

    const float invB = 1.0f / (float)nrows;
    const float4* __restrict__ in4 = (const float4*)inputs;
    const int4*   __restrict__ tg4 = (const int4*)targets;
    const int4*   __restrict__ cs4 = (const int4*)cycle_states;

    float acc = 0.0f;                 // f32 partial: <=16 rows per thread, safe
    int nquad  = nrows >> 2;          // 4 rows per iteration
    int stride = gridDim.x * blockDim.x;
    for (int q = blockIdx.x * blockDim.x + threadIdx.x; q < nquad; q += stride) {
        float4 ia = in4[3 * q + 0];
        float4 ib = in4[3 * q + 1];
        float4 ic = in4[3 * q + 2];
        int4   ta = tg4[3 * q + 0];
        int4   tb = tg4[3 * q + 1];
        int4   tc = tg4[3 * q + 2];
        int4   cs = cs4[q];

        // rows: (ia.x,ia.y,ia.z) (ia.w,ib.x,ib.y) (ib.z,ib.w,ic.x) (ic.y,ic.z,ic.w)
        acc += row_term(ia.x, ia.y, ia.z, ta.x, ta.y, ta.z, cs.x, w, invB)
             + row_term(ia.w, ib.x, ib.y, ta.w, tb.x, tb.y, cs.y, w, invB)
             + row_term(ib.z, ib.w, ic.x, tb.z, tb.w, tc.x, cs.z, w, invB)
             + row_term(ic.y, ic.z, ic.w, tc.y, tc.z, tc.w, cs.w, w, invB);
    }

    // intra-block reduce in double (f32 partials promoted here)
    double dacc = (double)acc;
    #pragma unroll
    for (int o = 16; o; o >>= 1)
        dacc += __shfl_down_sync(0xffffffffu, dacc, o);

    __shared__ double sm[8];
    if ((threadIdx.x & 31) == 0) sm[threadIdx.x >> 5] = dacc;
    __syncthreads();

    __shared__ bool s_last;
    if (threadIdx.x == 0) {
        double v = sm[0];
        #pragma unroll
        for (int i = 1; i < 8; i++) v += sm[i];
        g_part[blockIdx.x] = v;
        __threadfence();
        unsigned int t = atomicAdd(&g_ticket, 1u);
        s_last = (t == gridDim.x - 1);
        if (s_last) g_ticket = 0;   // reset for next graph replay
    }
    __syncthreads();

    // last block reduces all partials and writes the scalar
    if (s_last) {
        __threadfence();
        double v = 0.0;
        for (int i = threadIdx.x; i < (int)gridDim.x; i += 256)
            v += g_part[i];
        #pragma unroll
        for (int o = 16; o; o >>= 1)
            v += __shfl_down_sync(0xffffffffu, v, o);
        if ((threadIdx.x & 31) == 0) sm[threadIdx.x >> 5] = v;
        __syncthreads();
        if (threadIdx.x == 0) {
            double tot = sm[0];
            #pragma unroll
            for (int i = 1; i < 8; i++) tot += sm[i];
            out[0] = (float)tot;
        }
    }
}

extern "C" void kernel_launch(void* const* d_in, const int* in_sizes, int n_in,
                              void* d_out, int out_size) {
    const float* inputs       = (const float*)d_in[0];   // [B,3] f32
    const int*   targets      = (const int*)d_in[1];     // [B,3] i32
    const int*   cycle_states = (const int*)d_in[2];     // [B]   i32
    const float* weights      = (const float*)d_in[3];   // [7]   f32
    float* out = (float*)d_out;

    int nrows = in_sizes[0] / 3;  // 4,194,304

    const int threads = 256;
    int nquad = nrows >> 2;
    int blocks = (nquad + threads - 1) / threads;
    if (blocks > WAVE_BLOCKS) blocks = WAVE_BLOCKS;  // one full wave @ 8 blocks/SM
    fused_loss_kernel<<<blocks, threads>>>(inputs, targets, cycle_states,
                                           weights, out, nrows);
}